// round 12
// baseline (speedup 1.0000x reference)
#include <cuda_runtime.h>
#include <cuda_fp16.h>
#include <stdint.h>

#define N_NODES     50000
#define N_EDGES     500000
#define D_FEAT      128
#define OUT_CLASSES 64
#define PDIM        128   // [0:64) = Pu (+bias folded), [64:128) = Pv

// Per-node projections in fp16; 12.8 MB, L2-resident.
__device__ __align__(16) __half g_P[N_NODES * PDIM];

// ---------------------------------------------------------------------------
// Single-pass fp16 mma (legacy mma.sync — tcgen05 unavailable at compute_103).
// Error sources (measured, quadrature): fp16-P 2.07e-4, fp16-B 2.07e-4,
// fp16-A 2.07e-4 -> total 3.6e-4 (measured 3.595e-4) << 1e-3.
// W is converted to fp16 fragments INLINE per warp (no pre-split kernel —
// its 4.3us was pure launch overhead; W is 64KB fp32, L1-resident).
// ---------------------------------------------------------------------------
__device__ __forceinline__ void mma_f16(float d[4], const uint32_t a[4], const uint32_t b[2]) {
    asm volatile(
        "mma.sync.aligned.m16n8k16.row.col.f32.f16.f16.f32 "
        "{%0,%1,%2,%3}, {%4,%5,%6,%7}, {%8,%9}, {%0,%1,%2,%3};\n"
        : "+f"(d[0]), "+f"(d[1]), "+f"(d[2]), "+f"(d[3])
        : "r"(a[0]), "r"(a[1]), "r"(a[2]), "r"(a[3]), "r"(b[0]), "r"(b[1]));
}

// ---------------------------------------------------------------------------
// Kernel 1: node projection GEMM, single-pass fp16, inline W conversion.
//   P[n][j] = sum_k h[n][k] * Wn[j][k] (+ b[j] for j<64)
//   Wn[j][k] = (j<64) ? W[j][k] : W[j-64][128+k]
// Tile 64m x 128n x 128k; A (fp16) staged in smem (17.4KB); occ=4.
// B fragment for (bn,kc): n = n_base+bn*8+lr, k pairs kc*8+lc and kc*8+lc+4
// -> two float2 loads from the fp32 W row + two cvt to f16x2.
// ---------------------------------------------------------------------------
#define GM   64
#define ST   68   // uint32 per row (64 f16x2 pairs + 4 pad); 68 mod 32 = 4
#define GEMM_SMEM (64 * ST * 4)   // 17,408 B

__global__ __launch_bounds__(256, 4)
void node_gemm_f16(const float* __restrict__ h,
                   const float* __restrict__ W,
                   const float* __restrict__ b) {
    extern __shared__ uint32_t sh[];
    uint32_t* Ah = sh;   // [64][ST] f16x2 pairs, k-major

    const int tid = threadIdx.x;
    const int n0  = blockIdx.x * GM;

    // Stage A (h tile, 64 x 128 f32 -> f16x2)
    #pragma unroll
    for (int it = 0; it < 8; ++it) {
        int idx = tid + it * 256;          // 0..2047
        int r  = idx >> 5;                 // 0..63
        int c4 = idx & 31;                 // float4 index; k = c4*4
        int node = n0 + r;
        float4 v = make_float4(0.f, 0.f, 0.f, 0.f);
        if (node < N_NODES)
            v = __ldg((const float4*)&h[(size_t)node * D_FEAT + c4 * 4]);
        __half2 h0 = __floats2half2_rn(v.x, v.y);
        __half2 h1 = __floats2half2_rn(v.z, v.w);
        *(uint2*)&Ah[r * ST + c4 * 2] = make_uint2(*(uint32_t*)&h0, *(uint32_t*)&h1);
    }
    __syncthreads();

    const int wid    = tid >> 5;
    const int lane   = tid & 31;
    const int warp_m = wid & 1;        // 2 warps over 64 m
    const int warp_n = wid >> 1;       // 4 warps over 128 n
    const int m_base = warp_m * 32;
    const int n_base = warp_n * 32;
    const int lr = lane >> 2;          // 0..7
    const int lc = lane & 3;           // 0..3

    // Per-bn W row pointer (hoisted; lane-dependent n, warp covers 32 n-rows)
    const float* wrow[4];
    #pragma unroll
    for (int bn = 0; bn < 4; ++bn) {
        int n = n_base + bn * 8 + lr;
        wrow[bn] = (n < OUT_CLASSES)
            ? &W[(size_t)n * 256]
            : &W[(size_t)(n - OUT_CLASSES) * 256 + 128];
    }

    float acc[2][4][4];
    #pragma unroll
    for (int a = 0; a < 2; ++a)
        #pragma unroll
        for (int bn = 0; bn < 4; ++bn)
            #pragma unroll
            for (int c = 0; c < 4; ++c) acc[a][bn][c] = 0.0f;

    #pragma unroll 2
    for (int kc = 0; kc < 8; ++kc) {
        const int p0 = kc * 8 + lc;        // pair index within row

        // B fragments: inline load+convert from fp32 W (L1-resident).
        uint32_t bb[4][2];
        #pragma unroll
        for (int bn = 0; bn < 4; ++bn) {
            float2 w0 = __ldg((const float2*)&wrow[bn][2 * p0]);
            float2 w1 = __ldg((const float2*)&wrow[bn][2 * p0 + 8]);
            __half2 c0 = __floats2half2_rn(w0.x, w0.y);
            __half2 c1 = __floats2half2_rn(w1.x, w1.y);
            bb[bn][0] = *(uint32_t*)&c0;
            bb[bn][1] = *(uint32_t*)&c1;
        }

        uint32_t ah[2][4];
        #pragma unroll
        for (int am = 0; am < 2; ++am) {
            int base = (m_base + am * 16 + lr) * ST + kc * 8 + lc;
            ah[am][0] = Ah[base];
            ah[am][1] = Ah[base + 8 * ST];
            ah[am][2] = Ah[base + 4];
            ah[am][3] = Ah[base + 8 * ST + 4];
        }
        #pragma unroll
        for (int am = 0; am < 2; ++am)
            #pragma unroll
            for (int bn = 0; bn < 4; ++bn)
                mma_f16(acc[am][bn], ah[am], bb[bn]);
    }

    // Epilogue: fp16 P, bias folded into Pu columns.
    #pragma unroll
    for (int am = 0; am < 2; ++am) {
        int row = m_base + am * 16 + lr;
        #pragma unroll
        for (int bn = 0; bn < 4; ++bn) {
            int j = n_base + bn * 8 + 2 * lc;
            float bx = 0.f, by = 0.f;
            if (warp_n < 2) {
                float2 bv = __ldg((const float2*)&b[j]);
                bx = bv.x; by = bv.y;
            }
            int node = n0 + row;
            if (node < N_NODES) {
                __half2 v0 = __floats2half2_rn(acc[am][bn][0] + bx,
                                               acc[am][bn][1] + by);
                *(__half2*)&g_P[(size_t)node * PDIM + j] = v0;
            }
            int node2 = n0 + row + 8;
            if (node2 < N_NODES) {
                __half2 v1 = __floats2half2_rn(acc[am][bn][2] + bx,
                                               acc[am][bn][3] + by);
                *(__half2*)&g_P[(size_t)node2 * PDIM + j] = v1;
            }
        }
    }
}

// ---------------------------------------------------------------------------
// Kernel 2: edge scatter on fp16 P. 8 edges/warp (4 per half-warp), all
// index loads and all 8 row-gathers front-batched (MLP 8+). Streaming
// float4 output stores; guarded tail. At ~DRAM-write floor (~21us).
// ---------------------------------------------------------------------------
__global__ __launch_bounds__(256)
void edge_scatter_kernel(const void* __restrict__ srcp,
                         const void* __restrict__ dstp,
                         float* __restrict__ out) {
    __shared__ int s_is64;
    if (threadIdx.x == 0) {
        const long long* s64 = (const long long*)srcp;
        int ok = 1;
        #pragma unroll
        for (int i = 0; i < 8; ++i) {
            long long v = s64[i];
            if (v < 0 || v >= (long long)N_NODES) ok = 0;
        }
        s_is64 = ok;
    }
    __syncthreads();
    const int is64 = s_is64;

    const int warp = threadIdx.x >> 5;
    const int lane = threadIdx.x & 31;
    const int half = lane >> 4;
    const int sub  = lane & 15;
    const long long ebase = ((long long)blockIdx.x * 8 + warp) * 8 + half * 4;

    long long e[4], s[4], d[4];
    #pragma unroll
    for (int i = 0; i < 4; ++i) {
        e[i] = ebase + i;
        long long ec = e[i] < N_EDGES ? e[i] : (long long)(N_EDGES - 1);
        if (is64) {
            s[i] = __ldg(&((const long long*)srcp)[ec]);
            d[i] = __ldg(&((const long long*)dstp)[ec]);
        } else {
            s[i] = __ldg(&((const int*)srcp)[ec]);
            d[i] = __ldg(&((const int*)dstp)[ec]);
        }
    }

    uint2 gu[4], gv[4];
    #pragma unroll
    for (int i = 0; i < 4; ++i) {
        gu[i] = *(const uint2*)&g_P[(size_t)s[i] * PDIM + sub * 4];
        gv[i] = *(const uint2*)&g_P[(size_t)d[i] * PDIM + OUT_CLASSES + sub * 4];
    }

    #pragma unroll
    for (int i = 0; i < 4; ++i) {
        float2 ux = __half22float2(*(__half2*)&gu[i].x);
        float2 uy = __half22float2(*(__half2*)&gu[i].y);
        float2 vx = __half22float2(*(__half2*)&gv[i].x);
        float2 vy = __half22float2(*(__half2*)&gv[i].y);
        float4 r = make_float4(ux.x + vx.x, ux.y + vx.y,
                               uy.x + vy.x, uy.y + vy.y);
        if (e[i] < N_EDGES)
            __stcs((float4*)&out[(size_t)e[i] * OUT_CLASSES + sub * 4], r);
    }
}

// ---------------------------------------------------------------------------
// Launch. Inputs: h[50000*128] f32, src[500000], dst[500000],
// W[64*256] f32, b[64] f32. Output: f32[500000*64].
// ---------------------------------------------------------------------------
extern "C" void kernel_launch(void* const* d_in, const int* in_sizes, int n_in,
                              void* d_out, int out_size) {
    const float* h   = (const float*)d_in[0];
    const void*  src = d_in[1];
    const void*  dst = d_in[2];
    const float* W   = (const float*)d_in[3];
    const float* b   = (const float*)d_in[4];
    float* out = (float*)d_out;
    (void)in_sizes; (void)n_in; (void)out_size;

    const int gemm_blocks = (N_NODES + GM - 1) / GM;   // 782
    node_gemm_f16<<<gemm_blocks, 256, GEMM_SMEM>>>(h, W, b);

    // 64 edges per block (8 warps x 8): ceil(500000/64) = 7813
    edge_scatter_kernel<<<(N_EDGES + 63) / 64, 256>>>(src, dst, out);
}

// round 13
// speedup vs baseline: 1.3005x; 1.3005x over previous
#include <cuda_runtime.h>
#include <cuda_fp16.h>
#include <stdint.h>

#define N_NODES     50000
#define N_EDGES     500000
#define D_FEAT      128
#define OUT_CLASSES 64
#define PDIM        128   // [0:64) = Pu (+bias folded), [64:128) = Pv

// Per-node projections in fp16; 12.8 MB, L2-resident.
__device__ __align__(16) __half g_P[N_NODES * PDIM];

// ---------------------------------------------------------------------------
// Single-pass fp16 mma (legacy mma.sync — tcgen05 unavailable at compute_103).
// Measured error quadrature: fp16-P + fp16-B + fp16-A = 3.595e-4 << 1e-3.
// W staged per-CTA into smem COALESCED (row-major LDG -> k-major fp16 pairs);
// B fragments then come from LDS, where the 8-row fragment scatter is
// conflict-free (stride 68). This removes the separate wsplit launch (r11)
// without r12's scattered-LDG regression.
// ---------------------------------------------------------------------------
__device__ __forceinline__ void mma_f16(float d[4], const uint32_t a[4], const uint32_t b[2]) {
    asm volatile(
        "mma.sync.aligned.m16n8k16.row.col.f32.f16.f16.f32 "
        "{%0,%1,%2,%3}, {%4,%5,%6,%7}, {%8,%9}, {%0,%1,%2,%3};\n"
        : "+f"(d[0]), "+f"(d[1]), "+f"(d[2]), "+f"(d[3])
        : "r"(a[0]), "r"(a[1]), "r"(a[2]), "r"(a[3]), "r"(b[0]), "r"(b[1]));
}

// ---------------------------------------------------------------------------
// Kernel 1: node projection GEMM, single-pass fp16, fused W staging.
//   P[n][j] = sum_k h[n][k] * Wn[j][k] (+ b[j] for j<64)
//   Wn[j][k] = (j<64) ? W[j][k] : W[j-64][128+k]
// Tile 64m x 128n x 128k. smem: A 64x68 + B 128x68 u32 pairs = 52.2KB, occ=4.
// ---------------------------------------------------------------------------
#define GM   64
#define ST   68   // uint32 per row (64 f16x2 pairs + 4 pad); 68 mod 32 = 4
#define GEMM_SMEM ((64 + 128) * ST * 4)   // 52,224 B

__global__ __launch_bounds__(256, 4)
void node_gemm_f16(const float* __restrict__ h,
                   const float* __restrict__ W,
                   const float* __restrict__ b) {
    extern __shared__ uint32_t sh[];
    uint32_t* Ah = sh;               // [64][ST]  f16x2 pairs, k-major
    uint32_t* Bs = sh + 64 * ST;     // [128][ST] f16x2 pairs, k-major

    const int tid = threadIdx.x;
    const int n0  = blockIdx.x * GM;

    // Stage A (h tile, 64 x 128 f32 -> f16x2), coalesced float4
    #pragma unroll
    for (int it = 0; it < 8; ++it) {
        int idx = tid + it * 256;          // 0..2047
        int r  = idx >> 5;                 // 0..63
        int c4 = idx & 31;                 // float4 index; k = c4*4
        int node = n0 + r;
        float4 v = make_float4(0.f, 0.f, 0.f, 0.f);
        if (node < N_NODES)
            v = __ldg((const float4*)&h[(size_t)node * D_FEAT + c4 * 4]);
        __half2 h0 = __floats2half2_rn(v.x, v.y);
        __half2 h1 = __floats2half2_rn(v.z, v.w);
        *(uint2*)&Ah[r * ST + c4 * 2] = make_uint2(*(uint32_t*)&h0, *(uint32_t*)&h1);
    }
    // Stage B (Wn, 128 x 128 f32 -> f16x2), coalesced float4 per row
    #pragma unroll
    for (int it = 0; it < 16; ++it) {
        int idx = tid + it * 256;          // 0..4095
        int j  = idx >> 5;                 // 0..127
        int c4 = idx & 31;
        const float* ws = (j < OUT_CLASSES)
            ? &W[(size_t)j * 256 + c4 * 4]
            : &W[(size_t)(j - OUT_CLASSES) * 256 + 128 + c4 * 4];
        float4 v = __ldg((const float4*)ws);
        __half2 h0 = __floats2half2_rn(v.x, v.y);
        __half2 h1 = __floats2half2_rn(v.z, v.w);
        *(uint2*)&Bs[j * ST + c4 * 2] = make_uint2(*(uint32_t*)&h0, *(uint32_t*)&h1);
    }
    __syncthreads();

    const int wid    = tid >> 5;
    const int lane   = tid & 31;
    const int warp_m = wid & 1;        // 2 warps over 64 m
    const int warp_n = wid >> 1;       // 4 warps over 128 n
    const int m_base = warp_m * 32;
    const int n_base = warp_n * 32;
    const int lr = lane >> 2;          // 0..7
    const int lc = lane & 3;           // 0..3

    float acc[2][4][4];
    #pragma unroll
    for (int a = 0; a < 2; ++a)
        #pragma unroll
        for (int bn = 0; bn < 4; ++bn)
            #pragma unroll
            for (int c = 0; c < 4; ++c) acc[a][bn][c] = 0.0f;

    #pragma unroll 2
    for (int kc = 0; kc < 8; ++kc) {
        const int p0 = kc * 8 + lc;

        // B fragments from smem: 8-row scatter, conflict-free at stride 68.
        uint32_t bb[4][2];
        #pragma unroll
        for (int bn = 0; bn < 4; ++bn) {
            int nb = (n_base + bn * 8 + lr) * ST + p0;
            bb[bn][0] = Bs[nb];
            bb[bn][1] = Bs[nb + 4];
        }

        uint32_t ah[2][4];
        #pragma unroll
        for (int am = 0; am < 2; ++am) {
            int base = (m_base + am * 16 + lr) * ST + p0;
            ah[am][0] = Ah[base];
            ah[am][1] = Ah[base + 8 * ST];
            ah[am][2] = Ah[base + 4];
            ah[am][3] = Ah[base + 8 * ST + 4];
        }
        #pragma unroll
        for (int am = 0; am < 2; ++am)
            #pragma unroll
            for (int bn = 0; bn < 4; ++bn)
                mma_f16(acc[am][bn], ah[am], bb[bn]);
    }

    // Epilogue: fp16 P, bias folded into Pu columns.
    #pragma unroll
    for (int am = 0; am < 2; ++am) {
        int row = m_base + am * 16 + lr;
        #pragma unroll
        for (int bn = 0; bn < 4; ++bn) {
            int j = n_base + bn * 8 + 2 * lc;
            float bx = 0.f, by = 0.f;
            if (warp_n < 2) {
                float2 bv = __ldg((const float2*)&b[j]);
                bx = bv.x; by = bv.y;
            }
            int node = n0 + row;
            if (node < N_NODES) {
                __half2 v0 = __floats2half2_rn(acc[am][bn][0] + bx,
                                               acc[am][bn][1] + by);
                *(__half2*)&g_P[(size_t)node * PDIM + j] = v0;
            }
            int node2 = n0 + row + 8;
            if (node2 < N_NODES) {
                __half2 v1 = __floats2half2_rn(acc[am][bn][2] + bx,
                                               acc[am][bn][3] + by);
                *(__half2*)&g_P[(size_t)node2 * PDIM + j] = v1;
            }
        }
    }
}

// ---------------------------------------------------------------------------
// Kernel 2: edge scatter on fp16 P. 8 edges/warp (4 per half-warp), all
// index loads and all 8 row-gathers front-batched (MLP 8+). All index math
// in int32 (edge ids < 2^31, node ids < 50000) to trim the ALU pipe.
// Streaming float4 output stores; guarded tail.
// ---------------------------------------------------------------------------
__global__ __launch_bounds__(256)
void edge_scatter_kernel(const void* __restrict__ srcp,
                         const void* __restrict__ dstp,
                         float* __restrict__ out) {
    __shared__ int s_is64;
    if (threadIdx.x == 0) {
        const long long* s64 = (const long long*)srcp;
        int ok = 1;
        #pragma unroll
        for (int i = 0; i < 8; ++i) {
            long long v = s64[i];
            if (v < 0 || v >= (long long)N_NODES) ok = 0;
        }
        s_is64 = ok;
    }
    __syncthreads();
    const int is64 = s_is64;

    const int warp = threadIdx.x >> 5;
    const int lane = threadIdx.x & 31;
    const int half = lane >> 4;
    const int sub  = lane & 15;
    const int ebase = (blockIdx.x * 8 + warp) * 8 + half * 4;

    int e[4], s[4], d[4];
    #pragma unroll
    for (int i = 0; i < 4; ++i) {
        e[i] = ebase + i;
        int ec = e[i] < N_EDGES ? e[i] : (N_EDGES - 1);
        if (is64) {
            s[i] = (int)__ldg(&((const long long*)srcp)[ec]);
            d[i] = (int)__ldg(&((const long long*)dstp)[ec]);
        } else {
            s[i] = __ldg(&((const int*)srcp)[ec]);
            d[i] = __ldg(&((const int*)dstp)[ec]);
        }
    }

    uint2 gu[4], gv[4];
    #pragma unroll
    for (int i = 0; i < 4; ++i) {
        gu[i] = *(const uint2*)&g_P[(unsigned)s[i] * PDIM + sub * 4];
        gv[i] = *(const uint2*)&g_P[(unsigned)d[i] * PDIM + OUT_CLASSES + sub * 4];
    }

    #pragma unroll
    for (int i = 0; i < 4; ++i) {
        float2 ux = __half22float2(*(__half2*)&gu[i].x);
        float2 uy = __half22float2(*(__half2*)&gu[i].y);
        float2 vx = __half22float2(*(__half2*)&gv[i].x);
        float2 vy = __half22float2(*(__half2*)&gv[i].y);
        float4 r = make_float4(ux.x + vx.x, ux.y + vx.y,
                               uy.x + vy.x, uy.y + vy.y);
        if (e[i] < N_EDGES)
            __stcs((float4*)&out[(size_t)(unsigned)e[i] * OUT_CLASSES + sub * 4], r);
    }
}

// ---------------------------------------------------------------------------
// Launch. Inputs: h[50000*128] f32, src[500000], dst[500000],
// W[64*256] f32, b[64] f32. Output: f32[500000*64].
// ---------------------------------------------------------------------------
extern "C" void kernel_launch(void* const* d_in, const int* in_sizes, int n_in,
                              void* d_out, int out_size) {
    const float* h   = (const float*)d_in[0];
    const void*  src = d_in[1];
    const void*  dst = d_in[2];
    const float* W   = (const float*)d_in[3];
    const float* b   = (const float*)d_in[4];
    float* out = (float*)d_out;
    (void)in_sizes; (void)n_in; (void)out_size;

    cudaFuncSetAttribute(node_gemm_f16,
                         cudaFuncAttributeMaxDynamicSharedMemorySize, GEMM_SMEM);

    const int gemm_blocks = (N_NODES + GM - 1) / GM;   // 782
    node_gemm_f16<<<gemm_blocks, 256, GEMM_SMEM>>>(h, W, b);

    // 64 edges per block (8 warps x 8): ceil(500000/64) = 7813
    edge_scatter_kernel<<<(N_EDGES + 63) / 64, 256>>>(src, dst, out);
}